// round 2
// baseline (speedup 1.0000x reference)
#include <cuda_runtime.h>
#include <cstdint>

#define NNODES  100000
#define NEDGES  1600000
#define NGRAPHS 64
#define EPS     1e-5f
#define NCHUNK  ((NNODES + 511) / 512)   // 196

// ---------------- device scratch (no allocations allowed) ----------------
__device__ int   g_deg [NNODES];
__device__ int   g_roff[NNODES];
__device__ int   g_cur [NNODES];
__device__ int   g_csr [NEDGES];
__device__ int   g_bsum [256];
__device__ int   g_bbase[256];
__device__ __align__(16) float g_h1[NNODES * 32];
__device__ __align__(16) float g_h2[NNODES * 64];
__device__ __align__(16) float g_h3[(size_t)NNODES * 128];
__device__ __align__(16) float g_stats[448];   // L1: sum@0 sq@32 | L2: sum@64 sq@128 | L3: sum@192 sq@320
__device__ __align__(16) float g_scale[128];
__device__ __align__(16) float g_shift[128];
__device__ __align__(16) float g_pool[NGRAPHS * 128];
__device__ float g_cntg[NGRAPHS];

__device__ __forceinline__ void red_add_v4(float* addr, float a, float b, float c, float d) {
    asm volatile("red.global.add.v4.f32 [%0], {%1,%2,%3,%4};"
                 :: "l"(addr), "f"(a), "f"(b), "f"(c), "f"(d) : "memory");
}

// ---------------- CSR build ----------------
__global__ void k_deg(const int* __restrict__ dst, int e) {
    int i = blockIdx.x * blockDim.x + threadIdx.x;
    if (i < e) atomicAdd(&g_deg[dst[i]], 1);
}

__global__ void k_chunks() {
    __shared__ int s[512];
    int tid = threadIdx.x;
    int i = blockIdx.x * 512 + tid;
    s[tid] = (i < NNODES) ? g_deg[i] : 0;
    __syncthreads();
    for (int off = 256; off > 0; off >>= 1) {
        if (tid < off) s[tid] += s[tid + off];
        __syncthreads();
    }
    if (tid == 0) g_bsum[blockIdx.x] = s[0];
}

__global__ void k_scanbase() {
    int run = 0;
    for (int i = 0; i < NCHUNK; i++) { g_bbase[i] = run; run += g_bsum[i]; }
}

__global__ void k_local() {
    __shared__ int s[512];
    int tid = threadIdx.x;
    int i = blockIdx.x * 512 + tid;
    int v = (i < NNODES) ? g_deg[i] : 0;
    s[tid] = v;
    __syncthreads();
    for (int off = 1; off < 512; off <<= 1) {
        int t = (tid >= off) ? s[tid - off] : 0;
        __syncthreads();
        s[tid] += t;
        __syncthreads();
    }
    if (i < NNODES) {
        int r = g_bbase[blockIdx.x] + s[tid] - v;   // exclusive
        g_roff[i] = r;
        g_cur[i]  = r;
    }
}

__global__ void k_fill(const int* __restrict__ src, const int* __restrict__ dst, int e) {
    int i = blockIdx.x * blockDim.x + threadIdx.x;
    if (i < e) {
        int d = dst[i];
        int pos = atomicAdd(&g_cur[d], 1);
        g_csr[pos] = src[i];
    }
}

// ---------------- layer 1: din=2 -> dout=32 (thread per node) ----------------
__global__ __launch_bounds__(256) void k_layer1(const float* __restrict__ x,
                                                const float* __restrict__ Wl,
                                                const float* __restrict__ bl,
                                                const float* __restrict__ Wr) {
    __shared__ float sWl[64], sWr[64], sbl[32];
    int tid = threadIdx.x;
    if (tid < 64) { sWl[tid] = Wl[tid]; sWr[tid] = Wr[tid]; }
    if (tid < 32) sbl[tid] = bl[tid];
    __syncthreads();
    int n = blockIdx.x * 256 + tid;
    if (n >= NNODES) return;
    const float2* x2 = (const float2*)x;
    int st = g_roff[n], d = g_deg[n];
    float a0 = 0.f, a1 = 0.f;
    int k = 0;
    for (; k + 4 <= d; k += 4) {
        int s0 = g_csr[st + k], s1 = g_csr[st + k + 1], s2 = g_csr[st + k + 2], s3 = g_csr[st + k + 3];
        float2 v0 = x2[s0], v1 = x2[s1], v2 = x2[s2], v3 = x2[s3];
        a0 += v0.x + v1.x + v2.x + v3.x;
        a1 += v0.y + v1.y + v2.y + v3.y;
    }
    for (; k < d; ++k) { float2 v = x2[g_csr[st + k]]; a0 += v.x; a1 += v.y; }
    float inv = 1.f / (float)max(d, 1);
    a0 *= inv; a1 *= inv;
    float2 xv = x2[n];
    float z[32];
#pragma unroll
    for (int j = 0; j < 32; j++)
        z[j] = sbl[j] + a0 * sWl[j] + a1 * sWl[32 + j] + xv.x * sWr[j] + xv.y * sWr[32 + j];
    float* outp = &g_h1[(size_t)n * 32];
#pragma unroll
    for (int j = 0; j < 32; j += 4)
        *(float4*)&outp[j] = make_float4(z[j], z[j + 1], z[j + 2], z[j + 3]);
}

// ---------------- layer 2: din=32 -> dout=64 (warp per node) ----------------
__global__ __launch_bounds__(256) void k_layer2(const float* __restrict__ hin,
                                                const float* __restrict__ Wl,
                                                const float* __restrict__ bl,
                                                const float* __restrict__ Wr,
                                                float* __restrict__ out) {
    __shared__ float sWl[2048], sWr[2048], sbl[64];
    __shared__ float sAgg[8][32], sX[8][32];
    int tid = threadIdx.x;
    for (int i = tid; i < 2048; i += 256) { sWl[i] = Wl[i]; sWr[i] = Wr[i]; }
    if (tid < 64) sbl[tid] = bl[tid];
    __syncthreads();
    int gw = (blockIdx.x * 256 + tid) >> 5;
    if (gw >= NNODES) return;
    int lane = tid & 31, w = tid >> 5;
    int st = g_roff[gw], d = g_deg[gw];
    float acc = 0.f;
    int k = 0;
    for (; k + 4 <= d; k += 4) {
        int s0 = g_csr[st + k], s1 = g_csr[st + k + 1], s2 = g_csr[st + k + 2], s3 = g_csr[st + k + 3];
        float v0 = hin[(size_t)s0 * 32 + lane];
        float v1 = hin[(size_t)s1 * 32 + lane];
        float v2 = hin[(size_t)s2 * 32 + lane];
        float v3 = hin[(size_t)s3 * 32 + lane];
        acc += v0 + v1 + v2 + v3;
    }
    for (; k < d; ++k) acc += hin[(size_t)g_csr[st + k] * 32 + lane];
    float inv = 1.f / (float)max(d, 1);
    sAgg[w][lane] = acc * inv;
    sX[w][lane]   = hin[(size_t)gw * 32 + lane];
    __syncwarp();
    float o0 = sbl[2 * lane], o1 = sbl[2 * lane + 1];
#pragma unroll
    for (int i = 0; i < 32; i++) {
        float a = sAgg[w][i], xv = sX[w][i];
        float2 wl = *(const float2*)&sWl[i * 64 + 2 * lane];
        float2 wr = *(const float2*)&sWr[i * 64 + 2 * lane];
        o0 += a * wl.x + xv * wr.x;
        o1 += a * wl.y + xv * wr.y;
    }
    *(float2*)&out[(size_t)gw * 64 + 2 * lane] = make_float2(o0, o1);
}

// ---------------- layer 3: din=64 -> dout=128 (warp per node, dyn smem) ----------------
__global__ __launch_bounds__(256) void k_layer3(const float* __restrict__ hin,
                                                const float* __restrict__ Wl,
                                                const float* __restrict__ bl,
                                                const float* __restrict__ Wr,
                                                float* __restrict__ out) {
    extern __shared__ float sm[];
    float* sWl  = sm;            // 8192
    float* sWr  = sm + 8192;     // 8192
    float* sbl  = sm + 16384;    // 128
    float* sAgg = sm + 16512;    // 8*64
    float* sX   = sm + 17024;    // 8*64  -> total 17536 floats = 70144 B
    int tid = threadIdx.x;
    for (int i = tid; i < 8192; i += 256) { sWl[i] = Wl[i]; sWr[i] = Wr[i]; }
    if (tid < 128) sbl[tid] = bl[tid];
    __syncthreads();
    int gw = (blockIdx.x * 256 + tid) >> 5;
    if (gw >= NNODES) return;
    int lane = tid & 31, w = tid >> 5;
    int st = g_roff[gw], d = g_deg[gw];
    const float2* h2v = (const float2*)hin;
    float a0 = 0.f, a1 = 0.f;
    int k = 0;
    for (; k + 4 <= d; k += 4) {
        int s0 = g_csr[st + k], s1 = g_csr[st + k + 1], s2 = g_csr[st + k + 2], s3 = g_csr[st + k + 3];
        float2 v0 = h2v[(size_t)s0 * 32 + lane];
        float2 v1 = h2v[(size_t)s1 * 32 + lane];
        float2 v2 = h2v[(size_t)s2 * 32 + lane];
        float2 v3 = h2v[(size_t)s3 * 32 + lane];
        a0 += v0.x + v1.x + v2.x + v3.x;
        a1 += v0.y + v1.y + v2.y + v3.y;
    }
    for (; k < d; ++k) { float2 v = h2v[(size_t)g_csr[st + k] * 32 + lane]; a0 += v.x; a1 += v.y; }
    float inv = 1.f / (float)max(d, 1);
    *(float2*)&sAgg[w * 64 + 2 * lane] = make_float2(a0 * inv, a1 * inv);
    *(float2*)&sX[w * 64 + 2 * lane]   = h2v[(size_t)gw * 32 + lane];
    __syncwarp();
    float4 o = *(const float4*)&sbl[4 * lane];
#pragma unroll
    for (int i = 0; i < 64; i++) {
        float a = sAgg[w * 64 + i], xv = sX[w * 64 + i];
        float4 wl = *(const float4*)&sWl[i * 128 + 4 * lane];
        float4 wr = *(const float4*)&sWr[i * 128 + 4 * lane];
        o.x += a * wl.x + xv * wr.x;
        o.y += a * wl.y + xv * wr.y;
        o.z += a * wl.z + xv * wr.z;
        o.w += a * wl.w + xv * wr.w;
    }
    *(float4*)&out[(size_t)gw * 128 + 4 * lane] = o;
}

// ---------------- batchnorm: stats / finalize / normalize ----------------
template <int D>
__global__ __launch_bounds__(256) void k_stats(const float* __restrict__ z,
                                               float* __restrict__ gsum, float* __restrict__ gsq) {
    constexpr int CPG = D / 4;
    constexpr int RPB = 256 / CPG;
    __shared__ float4 ss[256], sq[256];
    int tid = threadIdx.x;
    int c4 = tid & (CPG - 1);
    int rp = tid / CPG;
    float4 s = make_float4(0, 0, 0, 0), q = make_float4(0, 0, 0, 0);
    const float4* z4 = (const float4*)z;
    for (int r = blockIdx.x * RPB + rp; r < NNODES; r += gridDim.x * RPB) {
        float4 v = z4[(size_t)r * CPG + c4];
        s.x += v.x; s.y += v.y; s.z += v.z; s.w += v.w;
        q.x += v.x * v.x; q.y += v.y * v.y; q.z += v.z * v.z; q.w += v.w * v.w;
    }
    ss[tid] = s; sq[tid] = q;
    __syncthreads();
    for (int off = 128; off >= CPG; off >>= 1) {
        if (tid < off) {
            ss[tid].x += ss[tid + off].x; ss[tid].y += ss[tid + off].y;
            ss[tid].z += ss[tid + off].z; ss[tid].w += ss[tid + off].w;
            sq[tid].x += sq[tid + off].x; sq[tid].y += sq[tid + off].y;
            sq[tid].z += sq[tid + off].z; sq[tid].w += sq[tid + off].w;
        }
        __syncthreads();
    }
    if (tid < CPG) {
        red_add_v4(&gsum[tid * 4], ss[tid].x, ss[tid].y, ss[tid].z, ss[tid].w);
        red_add_v4(&gsq [tid * 4], sq[tid].x, sq[tid].y, sq[tid].z, sq[tid].w);
    }
}

template <int D>
__global__ void k_finalize(const float* __restrict__ gsum, const float* __restrict__ gsq,
                           const float* __restrict__ gam, const float* __restrict__ bet) {
    int c = threadIdx.x;
    float mean = gsum[c] * (1.f / NNODES);
    float var  = gsq[c] * (1.f / NNODES) - mean * mean;
    float sc = gam[c] * rsqrtf(var + EPS);
    g_scale[c] = sc;
    g_shift[c] = bet[c] - mean * sc;
}

template <int D>
__global__ __launch_bounds__(256) void k_bnrelu(float* __restrict__ z) {
    constexpr int CPG = D / 4;
    const int total = NNODES * CPG;
    float4* z4 = (float4*)z;
    for (int idx = blockIdx.x * blockDim.x + threadIdx.x; idx < total; idx += gridDim.x * blockDim.x) {
        int c = (idx % CPG) * 4;
        float4 v = z4[idx];
        float4 sc = *(const float4*)&g_scale[c];
        float4 sh = *(const float4*)&g_shift[c];
        v.x = fmaxf(v.x * sc.x + sh.x, 0.f);
        v.y = fmaxf(v.y * sc.y + sh.y, 0.f);
        v.z = fmaxf(v.z * sc.z + sh.z, 0.f);
        v.w = fmaxf(v.w * sc.w + sh.w, 0.f);
        z4[idx] = v;
    }
}

// ---------------- pooling + MLP ----------------
__global__ void k_cnt(const int* __restrict__ batch) {
    int n = blockIdx.x * blockDim.x + threadIdx.x;
    if (n >= NNODES) return;
    int g = batch[n];
    unsigned act = __activemask();
    unsigned mask = __match_any_sync(act, g);
    int leader = __ffs(mask) - 1;
    if ((threadIdx.x & 31) == leader) atomicAdd(&g_cntg[g], (float)__popc(mask));
}

__global__ void k_pool(const int* __restrict__ batch) {
    int idx = blockIdx.x * blockDim.x + threadIdx.x;   // over NNODES*32 float4s
    if (idx >= NNODES * 32) return;
    int row = idx >> 5, c4 = idx & 31;
    int g = batch[row];
    float4 v = ((const float4*)g_h3)[idx];
    red_add_v4(&g_pool[g * 128 + c4 * 4], v.x, v.y, v.z, v.w);
}

__global__ void k_mlp(const float* __restrict__ Wf1, const float* __restrict__ bf1,
                      const float* __restrict__ Wf2, const float* __restrict__ bf2,
                      float* __restrict__ out) {
    __shared__ float sp[128];
    __shared__ float sh[64];
    int g = blockIdx.x, tid = threadIdx.x;
    float inv = 1.f / fmaxf(g_cntg[g], 1.f);
    sp[tid] = g_pool[g * 128 + tid] * inv;
    __syncthreads();
    if (tid < 64) {
        float acc = bf1[tid];
#pragma unroll 8
        for (int i = 0; i < 128; i++) acc += sp[i] * Wf1[i * 64 + tid];
        acc = fmaxf(acc, 0.f);
        sh[tid] = acc * Wf2[tid];
    }
    __syncthreads();
    if (tid < 32) {
        float v = sh[tid] + sh[tid + 32];
        for (int o = 16; o; o >>= 1) v += __shfl_down_sync(0xffffffffu, v, o);
        if (tid == 0) out[g] = v + bf2[0];
    }
}

// ---------------- launch ----------------
extern "C" void kernel_launch(void* const* d_in, const int* in_sizes, int n_in,
                              void* d_out, int out_size) {
    const float* x     = (const float*)d_in[0];
    const int*   ei    = (const int*)d_in[1];   // jax int64 -> int32 (x64 disabled)
    const int*   batch = (const int*)d_in[2];
    const float* Wl1 = (const float*)d_in[3];
    const float* bl1 = (const float*)d_in[4];
    const float* Wr1 = (const float*)d_in[5];
    const float* g1  = (const float*)d_in[6];
    const float* be1 = (const float*)d_in[7];
    const float* Wl2 = (const float*)d_in[8];
    const float* bl2 = (const float*)d_in[9];
    const float* Wr2 = (const float*)d_in[10];
    const float* g2  = (const float*)d_in[11];
    const float* be2 = (const float*)d_in[12];
    const float* Wl3 = (const float*)d_in[13];
    const float* bl3 = (const float*)d_in[14];
    const float* Wr3 = (const float*)d_in[15];
    const float* g3  = (const float*)d_in[16];
    const float* be3 = (const float*)d_in[17];
    const float* Wf1 = (const float*)d_in[18];
    const float* bf1 = (const float*)d_in[19];
    const float* Wf2 = (const float*)d_in[20];
    const float* bf2 = (const float*)d_in[21];

    int E = in_sizes[1] / 2;
    const int* src = ei;
    const int* dst = ei + E;

    void *p_deg, *p_stats, *p_pool, *p_cnt, *p_h1, *p_h2, *p_h3;
    cudaGetSymbolAddress(&p_deg,   g_deg);
    cudaGetSymbolAddress(&p_stats, g_stats);
    cudaGetSymbolAddress(&p_pool,  g_pool);
    cudaGetSymbolAddress(&p_cnt,   g_cntg);
    cudaGetSymbolAddress(&p_h1,    g_h1);
    cudaGetSymbolAddress(&p_h2,    g_h2);
    cudaGetSymbolAddress(&p_h3,    g_h3);
    float* h1 = (float*)p_h1;
    float* h2 = (float*)p_h2;
    float* h3 = (float*)p_h3;
    float* st = (float*)p_stats;

    cudaMemsetAsync(p_deg,   0, NNODES * sizeof(int));
    cudaMemsetAsync(p_stats, 0, 448 * sizeof(float));
    cudaMemsetAsync(p_pool,  0, NGRAPHS * 128 * sizeof(float));
    cudaMemsetAsync(p_cnt,   0, NGRAPHS * sizeof(float));

    int eb = (E + 255) / 256;
    k_deg<<<eb, 256>>>(dst, E);
    k_chunks<<<NCHUNK, 512>>>();
    k_scanbase<<<1, 1>>>();
    k_local<<<NCHUNK, 512>>>();
    k_fill<<<eb, 256>>>(src, dst, E);

    const int NB = (NNODES + 255) / 256;       // 391
    const int WB = (NNODES * 32 + 255) / 256;  // warp-per-node grids

    // layer 1
    k_layer1<<<NB, 256>>>(x, Wl1, bl1, Wr1);
    k_stats<32><<<392, 256>>>(h1, st + 0, st + 32);
    k_finalize<32><<<1, 32>>>(st + 0, st + 32, g1, be1);
    k_bnrelu<32><<<392, 256>>>(h1);

    // layer 2
    k_layer2<<<WB, 256>>>(h1, Wl2, bl2, Wr2, h2);
    k_stats<64><<<392, 256>>>(h2, st + 64, st + 128);
    k_finalize<64><<<1, 64>>>(st + 64, st + 128, g2, be2);
    k_bnrelu<64><<<392, 256>>>(h2);

    // layer 3 (needs >48KB dynamic smem)
    cudaFuncSetAttribute(k_layer3, cudaFuncAttributeMaxDynamicSharedMemorySize, 70144);
    k_layer3<<<WB, 256, 70144>>>(h2, Wl3, bl3, Wr3, h3);
    k_stats<128><<<392, 256>>>(h3, st + 192, st + 320);
    k_finalize<128><<<1, 128>>>(st + 192, st + 320, g3, be3);
    k_bnrelu<128><<<392, 256>>>(h3);

    // pool + head
    k_cnt<<<NB, 256>>>(batch);
    k_pool<<<(NNODES * 32 + 255) / 256, 256>>>(batch);
    k_mlp<<<NGRAPHS, 128>>>(Wf1, bf1, Wf2, bf2, (float*)d_out);
}

// round 3
// speedup vs baseline: 1.6452x; 1.6452x over previous
#include <cuda_runtime.h>
#include <cstdint>

#define NNODES  100000
#define NEDGES  1600000
#define NGRAPHS 64
#define EPS     1e-5f
#define NCHUNK  ((NNODES + 511) / 512)   // 196

typedef unsigned long long u64;

// ---------------- device scratch ----------------
__device__ int   g_deg [NNODES];
__device__ int   g_roff[NNODES];
__device__ int   g_cur [NNODES];
__device__ int   g_csr [NEDGES];
__device__ int   g_bsum [256];
__device__ int   g_bbase[256];
__device__ __align__(16) float g_h1[NNODES * 32];
__device__ __align__(16) float g_h2[NNODES * 64];
__device__ __align__(16) float g_h3[(size_t)NNODES * 128];
__device__ __align__(16) float g_stats[448];   // L1 sum@0 sq@32 | L2 sum@64 sq@128 | L3 sum@192 sq@320
__device__ __align__(16) float g_pool[NGRAPHS * 128];
__device__ float g_cntg[NGRAPHS];

// ---------------- helpers ----------------
__device__ __forceinline__ u64 ffma2(u64 a, u64 b, u64 c) {
    u64 d;
    asm("fma.rn.f32x2 %0, %1, %2, %3;" : "=l"(d) : "l"(a), "l"(b), "l"(c));
    return d;
}
__device__ __forceinline__ u64 pack2(float lo, float hi) {
    u64 r;
    asm("mov.b64 %0, {%1, %2};" : "=l"(r) : "f"(lo), "f"(hi));
    return r;
}
__device__ __forceinline__ float2 unpack2(u64 v) {
    float2 r;
    asm("mov.b64 {%0, %1}, %2;" : "=f"(r.x), "=f"(r.y) : "l"(v));
    return r;
}
__device__ __forceinline__ void red_f32(float* addr, float v) {
    asm volatile("red.global.add.f32 [%0], %1;" :: "l"(addr), "f"(v) : "memory");
}
__device__ __forceinline__ void red_add_v4(float* addr, float a, float b, float c, float d) {
    asm volatile("red.global.add.v4.f32 [%0], {%1,%2,%3,%4};"
                 :: "l"(addr), "f"(a), "f"(b), "f"(c), "f"(d) : "memory");
}

// ---------------- zero scratch (replaces 4 memsets) ----------------
__global__ void k_zero() {
    int i = blockIdx.x * blockDim.x + threadIdx.x;
    int stride = gridDim.x * blockDim.x;
    for (int j = i; j < NNODES; j += stride) g_deg[j] = 0;
    if (i < 448) g_stats[i] = 0.f;
    if (i < NGRAPHS * 128) g_pool[i] = 0.f;
    if (i < NGRAPHS) g_cntg[i] = 0.f;
}

// ---------------- CSR build (+ per-graph node counts) ----------------
__global__ void k_deg(const int* __restrict__ dst, const int* __restrict__ batch, int e) {
    int i = blockIdx.x * blockDim.x + threadIdx.x;
    if (i < e) atomicAdd(&g_deg[dst[i]], 1);
    if (i < NNODES) {
        int g = batch[i];
        unsigned act = __activemask();
        unsigned mask = __match_any_sync(act, g);
        int leader = __ffs(mask) - 1;
        if ((threadIdx.x & 31) == leader) atomicAdd(&g_cntg[g], (float)__popc(mask));
    }
}

__global__ void k_chunks() {
    __shared__ int s[512];
    int tid = threadIdx.x;
    int i = blockIdx.x * 512 + tid;
    s[tid] = (i < NNODES) ? g_deg[i] : 0;
    __syncthreads();
    for (int off = 256; off > 0; off >>= 1) {
        if (tid < off) s[tid] += s[tid + off];
        __syncthreads();
    }
    if (tid == 0) g_bsum[blockIdx.x] = s[0];
}

__global__ void k_scanbase() {   // one block, parallel smem scan (was serial 1-thread)
    __shared__ int s[256];
    int tid = threadIdx.x;
    int v = (tid < NCHUNK) ? g_bsum[tid] : 0;
    s[tid] = v;
    __syncthreads();
    for (int off = 1; off < 256; off <<= 1) {
        int t = (tid >= off) ? s[tid - off] : 0;
        __syncthreads();
        s[tid] += t;
        __syncthreads();
    }
    if (tid < NCHUNK) g_bbase[tid] = s[tid] - v;
}

__global__ void k_local() {
    __shared__ int s[512];
    int tid = threadIdx.x;
    int i = blockIdx.x * 512 + tid;
    int v = (i < NNODES) ? g_deg[i] : 0;
    s[tid] = v;
    __syncthreads();
    for (int off = 1; off < 512; off <<= 1) {
        int t = (tid >= off) ? s[tid - off] : 0;
        __syncthreads();
        s[tid] += t;
        __syncthreads();
    }
    if (i < NNODES) {
        int r = g_bbase[blockIdx.x] + s[tid] - v;
        g_roff[i] = r;
        g_cur[i]  = r;
    }
}

__global__ void k_fill(const int* __restrict__ src, const int* __restrict__ dst, int e) {
    int i = blockIdx.x * blockDim.x + threadIdx.x;
    if (i < e) {
        int d = dst[i];
        int pos = atomicAdd(&g_cur[d], 1);
        g_csr[pos] = src[i];
    }
}

// ---------------- layer 1: 2 -> 32 (thread per node; weights broadcast) ----------------
__global__ __launch_bounds__(256) void k_layer1(const float* __restrict__ x,
                                                const float* __restrict__ Wl,
                                                const float* __restrict__ bl,
                                                const float* __restrict__ Wr) {
    __shared__ float sWl[64], sWr[64], sbl[32];
    int tid = threadIdx.x;
    if (tid < 64) { sWl[tid] = Wl[tid]; sWr[tid] = Wr[tid]; }
    if (tid < 32) sbl[tid] = bl[tid];
    __syncthreads();
    int n = blockIdx.x * 256 + tid;
    if (n >= NNODES) return;
    const float2* x2 = (const float2*)x;
    int st = g_roff[n], d = g_deg[n];
    float a0 = 0.f, a1 = 0.f;
    int k = 0;
    for (; k + 4 <= d; k += 4) {
        int s0 = g_csr[st + k], s1 = g_csr[st + k + 1], s2 = g_csr[st + k + 2], s3 = g_csr[st + k + 3];
        float2 v0 = x2[s0], v1 = x2[s1], v2 = x2[s2], v3 = x2[s3];
        a0 += v0.x + v1.x + v2.x + v3.x;
        a1 += v0.y + v1.y + v2.y + v3.y;
    }
    for (; k < d; ++k) { float2 v = x2[g_csr[st + k]]; a0 += v.x; a1 += v.y; }
    float inv = 1.f / (float)max(d, 1);
    a0 *= inv; a1 *= inv;
    float2 xv = x2[n];
    u64 A0 = pack2(a0, a0), A1 = pack2(a1, a1), X0 = pack2(xv.x, xv.x), X1 = pack2(xv.y, xv.y);
    float* outp = &g_h1[(size_t)n * 32];
#pragma unroll
    for (int jp = 0; jp < 16; jp += 2) {
        u64 t0 = *(const u64*)&sbl[2 * jp];
        u64 t1 = *(const u64*)&sbl[2 * jp + 2];
        t0 = ffma2(A0, *(const u64*)&sWl[2 * jp], t0);
        t1 = ffma2(A0, *(const u64*)&sWl[2 * jp + 2], t1);
        t0 = ffma2(A1, *(const u64*)&sWl[32 + 2 * jp], t0);
        t1 = ffma2(A1, *(const u64*)&sWl[32 + 2 * jp + 2], t1);
        t0 = ffma2(X0, *(const u64*)&sWr[2 * jp], t0);
        t1 = ffma2(X0, *(const u64*)&sWr[2 * jp + 2], t1);
        t0 = ffma2(X1, *(const u64*)&sWr[32 + 2 * jp], t0);
        t1 = ffma2(X1, *(const u64*)&sWr[32 + 2 * jp + 2], t1);
        ulonglong2 st2; st2.x = t0; st2.y = t1;
        *(ulonglong2*)&outp[2 * jp] = st2;
    }
}

// ---------------- stats for layer1 (separate cheap pass) ----------------
__global__ __launch_bounds__(256) void k_stats32(const float* __restrict__ z,
                                                 float* __restrict__ gsum, float* __restrict__ gsq) {
    constexpr int CPG = 8;     // float4 groups per row
    constexpr int RPB = 32;
    __shared__ float4 ss[256], sq[256];
    int tid = threadIdx.x;
    int c4 = tid & (CPG - 1);
    int rp = tid / CPG;
    float4 s = make_float4(0, 0, 0, 0), q = make_float4(0, 0, 0, 0);
    const float4* z4 = (const float4*)z;
    for (int r = blockIdx.x * RPB + rp; r < NNODES; r += gridDim.x * RPB) {
        float4 v = z4[(size_t)r * CPG + c4];
        s.x += v.x; s.y += v.y; s.z += v.z; s.w += v.w;
        q.x += v.x * v.x; q.y += v.y * v.y; q.z += v.z * v.z; q.w += v.w * v.w;
    }
    ss[tid] = s; sq[tid] = q;
    __syncthreads();
    for (int off = 128; off >= CPG; off >>= 1) {
        if (tid < off) {
            ss[tid].x += ss[tid + off].x; ss[tid].y += ss[tid + off].y;
            ss[tid].z += ss[tid + off].z; ss[tid].w += ss[tid + off].w;
            sq[tid].x += sq[tid + off].x; sq[tid].y += sq[tid + off].y;
            sq[tid].z += sq[tid + off].z; sq[tid].w += sq[tid + off].w;
        }
        __syncthreads();
    }
    if (tid < CPG) {
        red_add_v4(&gsum[tid * 4], ss[tid].x, ss[tid].y, ss[tid].z, ss[tid].w);
        red_add_v4(&gsq [tid * 4], sq[tid].x, sq[tid].y, sq[tid].z, sq[tid].w);
    }
}

// ---------------- fused finalize + bn + relu (in place) ----------------
template <int D>
__global__ __launch_bounds__(256) void k_bnrelu(float* __restrict__ z,
                                                const float* __restrict__ gsum, const float* __restrict__ gsq,
                                                const float* __restrict__ gam, const float* __restrict__ bet) {
    __shared__ float ssc[D], ssh[D];
    int tid = threadIdx.x;
    if (tid < D) {
        float mean = gsum[tid] * (1.f / NNODES);
        float var  = gsq[tid] * (1.f / NNODES) - mean * mean;
        float sc = gam[tid] * rsqrtf(var + EPS);
        ssc[tid] = sc;
        ssh[tid] = bet[tid] - mean * sc;
    }
    __syncthreads();
    constexpr int CPG = D / 4;
    const int total = NNODES * CPG;
    float4* z4 = (float4*)z;
    for (int idx = blockIdx.x * blockDim.x + tid; idx < total; idx += gridDim.x * blockDim.x) {
        int c = (idx % CPG) * 4;
        float4 v = z4[idx];
        float4 sc = *(const float4*)&ssc[c];
        float4 sh = *(const float4*)&ssh[c];
        v.x = fmaxf(v.x * sc.x + sh.x, 0.f);
        v.y = fmaxf(v.y * sc.y + sh.y, 0.f);
        v.z = fmaxf(v.z * sc.z + sh.z, 0.f);
        v.w = fmaxf(v.w * sc.w + sh.w, 0.f);
        z4[idx] = v;
    }
}

// ---------------- layer 2: 32 -> 64, 64 nodes/block, fused stats ----------------
__global__ __launch_bounds__(256) void k_layer2(const float* __restrict__ hin,
                                                const float* __restrict__ Wl,
                                                const float* __restrict__ bl,
                                                const float* __restrict__ Wr,
                                                float* __restrict__ out,
                                                float* __restrict__ gsum, float* __restrict__ gsq) {
    __shared__ float sWl[2048], sWr[2048], sbl[64];
    __shared__ float sAX[64 * 64];   // row rr: [rr*64 + 2*i]={agg_i, x_i}
    int tid = threadIdx.x, lane = tid & 31, w = tid >> 5;
    for (int i = tid; i < 2048; i += 256) { sWl[i] = Wl[i]; sWr[i] = Wr[i]; }
    if (tid < 64) sbl[tid] = bl[tid];
    int base = blockIdx.x * 64;
    // gather: warp w handles rows w*8 .. w*8+7
    for (int r = 0; r < 8; r++) {
        int rr = w * 8 + r;
        int node = base + rr;
        float2 axv = make_float2(0.f, 0.f);
        if (node < NNODES) {
            int st = g_roff[node], d = g_deg[node];
            float acc = 0.f;
            int k = 0;
            for (; k + 4 <= d; k += 4) {
                int s0 = g_csr[st + k], s1 = g_csr[st + k + 1], s2 = g_csr[st + k + 2], s3 = g_csr[st + k + 3];
                acc += hin[(size_t)s0 * 32 + lane] + hin[(size_t)s1 * 32 + lane]
                     + hin[(size_t)s2 * 32 + lane] + hin[(size_t)s3 * 32 + lane];
            }
            for (; k < d; ++k) acc += hin[(size_t)g_csr[st + k] * 32 + lane];
            axv.x = acc * (1.f / (float)max(d, 1));
            axv.y = hin[(size_t)node * 32 + lane];
        }
        *(float2*)&sAX[rr * 64 + 2 * lane] = axv;
    }
    __syncthreads();
    // matvec: thread = cols {2*lane, 2*lane+1} × 8 rows (warp w's rows)
    u64 acc[8];
    {
        u64 b = *(const u64*)&sbl[2 * lane];
#pragma unroll
        for (int r = 0; r < 8; r++) acc[r] = b;
    }
#pragma unroll 4
    for (int i = 0; i < 32; i++) {
        u64 wl = *(const u64*)&sWl[i * 64 + 2 * lane];
        u64 wr = *(const u64*)&sWr[i * 64 + 2 * lane];
#pragma unroll
        for (int r = 0; r < 8; r++) {
            float2 ax = *(const float2*)&sAX[(w * 8 + r) * 64 + 2 * i];
            acc[r] = ffma2(pack2(ax.x, ax.x), wl, acc[r]);
            acc[r] = ffma2(pack2(ax.y, ax.y), wr, acc[r]);
        }
    }
    // store + per-thread stats partials
    float s0 = 0.f, s1 = 0.f, q0 = 0.f, q1 = 0.f;
#pragma unroll
    for (int r = 0; r < 8; r++) {
        int node = base + w * 8 + r;
        if (node < NNODES) {
            float2 v = unpack2(acc[r]);
            *(float2*)&out[(size_t)node * 64 + 2 * lane] = v;
            s0 += v.x; s1 += v.y; q0 += v.x * v.x; q1 += v.y * v.y;
        }
    }
    __syncthreads();   // before reusing sAX
    float* sRed = sAX;  // [w][0..63]=sum, [w][64..127]=sq  (stride 128)
    sRed[w * 128 + 2 * lane]     = s0;
    sRed[w * 128 + 2 * lane + 1] = s1;
    sRed[w * 128 + 64 + 2 * lane]     = q0;
    sRed[w * 128 + 64 + 2 * lane + 1] = q1;
    __syncthreads();
    if (tid < 128) {
        int c = tid & 63;
        int off = (tid >= 64) ? 64 : 0;
        float a = 0.f;
#pragma unroll
        for (int w2 = 0; w2 < 8; w2++) a += sRed[w2 * 128 + off + c];
        red_f32((tid >= 64) ? &gsq[c] : &gsum[c], a);
    }
}

// ---------------- layer 3: 64 -> 128, 64 nodes/block, dyn smem, fused stats ----------------
#define SM3_WL 0
#define SM3_WR 8192
#define SM3_BL 16384
#define SM3_AX 16512
#define SM3_FLOATS (16512 + 8192)      // 24704 floats = 98816 B
__global__ __launch_bounds__(256) void k_layer3(const float* __restrict__ hin,
                                                const float* __restrict__ Wl,
                                                const float* __restrict__ bl,
                                                const float* __restrict__ Wr,
                                                float* __restrict__ out,
                                                float* __restrict__ gsum, float* __restrict__ gsq) {
    extern __shared__ float sm[];
    float* sWl = sm + SM3_WL;
    float* sWr = sm + SM3_WR;
    float* sbl = sm + SM3_BL;
    float* sAX = sm + SM3_AX;   // row rr: [rr*128 + 2*i]={agg_i, x_i}
    int tid = threadIdx.x, lane = tid & 31, w = tid >> 5;
    for (int i = tid; i < 8192; i += 256) { sWl[i] = Wl[i]; sWr[i] = Wr[i]; }
    if (tid < 128) sbl[tid] = bl[tid];
    int base = blockIdx.x * 64;
    const float2* h2v = (const float2*)hin;
    for (int r = 0; r < 8; r++) {
        int rr = w * 8 + r;
        int node = base + rr;
        float4 axv = make_float4(0.f, 0.f, 0.f, 0.f);
        if (node < NNODES) {
            int st = g_roff[node], d = g_deg[node];
            float a0 = 0.f, a1 = 0.f;
            int k = 0;
            for (; k + 4 <= d; k += 4) {
                int s0 = g_csr[st + k], s1 = g_csr[st + k + 1], s2 = g_csr[st + k + 2], s3 = g_csr[st + k + 3];
                float2 v0 = h2v[(size_t)s0 * 32 + lane];
                float2 v1 = h2v[(size_t)s1 * 32 + lane];
                float2 v2 = h2v[(size_t)s2 * 32 + lane];
                float2 v3 = h2v[(size_t)s3 * 32 + lane];
                a0 += v0.x + v1.x + v2.x + v3.x;
                a1 += v0.y + v1.y + v2.y + v3.y;
            }
            for (; k < d; ++k) { float2 v = h2v[(size_t)g_csr[st + k] * 32 + lane]; a0 += v.x; a1 += v.y; }
            float inv = 1.f / (float)max(d, 1);
            float2 hx = h2v[(size_t)node * 32 + lane];
            axv = make_float4(a0 * inv, hx.x, a1 * inv, hx.y);  // {agg_2l, x_2l, agg_2l+1, x_2l+1}
        }
        *(float4*)&sAX[rr * 128 + 4 * lane] = axv;
    }
    __syncthreads();
    // matvec: thread = cols {4*lane..4*lane+3} × 8 rows
    u64 a01[8], a23[8];
    {
        u64 b01 = *(const u64*)&sbl[4 * lane];
        u64 b23 = *(const u64*)&sbl[4 * lane + 2];
#pragma unroll
        for (int r = 0; r < 8; r++) { a01[r] = b01; a23[r] = b23; }
    }
#pragma unroll 2
    for (int i = 0; i < 64; i++) {
        ulonglong2 wl = *(const ulonglong2*)&sWl[i * 128 + 4 * lane];
        ulonglong2 wr = *(const ulonglong2*)&sWr[i * 128 + 4 * lane];
#pragma unroll
        for (int r = 0; r < 8; r++) {
            float2 ax = *(const float2*)&sAX[(w * 8 + r) * 128 + 2 * i];
            u64 A = pack2(ax.x, ax.x);
            u64 X = pack2(ax.y, ax.y);
            a01[r] = ffma2(A, wl.x, a01[r]);
            a23[r] = ffma2(A, wl.y, a23[r]);
            a01[r] = ffma2(X, wr.x, a01[r]);
            a23[r] = ffma2(X, wr.y, a23[r]);
        }
    }
    float s[4] = {0.f, 0.f, 0.f, 0.f}, q[4] = {0.f, 0.f, 0.f, 0.f};
#pragma unroll
    for (int r = 0; r < 8; r++) {
        int node = base + w * 8 + r;
        if (node < NNODES) {
            float2 v01 = unpack2(a01[r]);
            float2 v23 = unpack2(a23[r]);
            *(float4*)&out[(size_t)node * 128 + 4 * lane] = make_float4(v01.x, v01.y, v23.x, v23.y);
            s[0] += v01.x; s[1] += v01.y; s[2] += v23.x; s[3] += v23.y;
            q[0] += v01.x * v01.x; q[1] += v01.y * v01.y; q[2] += v23.x * v23.x; q[3] += v23.y * v23.y;
        }
    }
    __syncthreads();
    float* sRed = sAX;   // [w][0..127]=sum, [w][128..255]=sq  (stride 256, fits: 8*256 <= 8192)
#pragma unroll
    for (int k = 0; k < 4; k++) {
        sRed[w * 256 + 4 * lane + k]       = s[k];
        sRed[w * 256 + 128 + 4 * lane + k] = q[k];
    }
    __syncthreads();
    if (tid < 256) {
        int c = tid & 127;
        int off = (tid >= 128) ? 128 : 0;
        float a = 0.f;
#pragma unroll
        for (int w2 = 0; w2 < 8; w2++) a += sRed[w2 * 256 + off + c];
        red_f32((tid >= 128) ? &gsq[c] : &gsum[c], a);
    }
}

// ---------------- fused finalize3 + bn + relu + pool ----------------
__global__ __launch_bounds__(256) void k_bnpool(const int* __restrict__ batch,
                                                const float* __restrict__ gsum, const float* __restrict__ gsq,
                                                const float* __restrict__ gam, const float* __restrict__ bet) {
    __shared__ float ssc[128], ssh[128];
    int tid = threadIdx.x;
    if (tid < 128) {
        float mean = gsum[tid] * (1.f / NNODES);
        float var  = gsq[tid] * (1.f / NNODES) - mean * mean;
        float sc = gam[tid] * rsqrtf(var + EPS);
        ssc[tid] = sc;
        ssh[tid] = bet[tid] - mean * sc;
    }
    __syncthreads();
    int idx = blockIdx.x * 256 + tid;     // exact: NNODES*32 / 256 = 12500 blocks
    int row = idx >> 5, c4 = idx & 31;
    int c = c4 * 4;
    float4 v = ((const float4*)g_h3)[idx];
    float4 sc = *(const float4*)&ssc[c];
    float4 sh = *(const float4*)&ssh[c];
    v.x = fmaxf(v.x * sc.x + sh.x, 0.f);
    v.y = fmaxf(v.y * sc.y + sh.y, 0.f);
    v.z = fmaxf(v.z * sc.z + sh.z, 0.f);
    v.w = fmaxf(v.w * sc.w + sh.w, 0.f);
    int g = batch[row];
    red_add_v4(&g_pool[g * 128 + c], v.x, v.y, v.z, v.w);
}

// ---------------- head MLP ----------------
__global__ void k_mlp(const float* __restrict__ Wf1, const float* __restrict__ bf1,
                      const float* __restrict__ Wf2, const float* __restrict__ bf2,
                      float* __restrict__ out) {
    __shared__ float sp[128];
    __shared__ float sh[64];
    int g = blockIdx.x, tid = threadIdx.x;
    float inv = 1.f / fmaxf(g_cntg[g], 1.f);
    sp[tid] = g_pool[g * 128 + tid] * inv;
    __syncthreads();
    if (tid < 64) {
        float acc = bf1[tid];
#pragma unroll 8
        for (int i = 0; i < 128; i++) acc += sp[i] * Wf1[i * 64 + tid];
        acc = fmaxf(acc, 0.f);
        sh[tid] = acc * Wf2[tid];
    }
    __syncthreads();
    if (tid < 32) {
        float v = sh[tid] + sh[tid + 32];
        for (int o = 16; o; o >>= 1) v += __shfl_down_sync(0xffffffffu, v, o);
        if (tid == 0) out[g] = v + bf2[0];
    }
}

// ---------------- launch ----------------
extern "C" void kernel_launch(void* const* d_in, const int* in_sizes, int n_in,
                              void* d_out, int out_size) {
    const float* x     = (const float*)d_in[0];
    const int*   ei    = (const int*)d_in[1];
    const int*   batch = (const int*)d_in[2];
    const float* Wl1 = (const float*)d_in[3];
    const float* bl1 = (const float*)d_in[4];
    const float* Wr1 = (const float*)d_in[5];
    const float* g1  = (const float*)d_in[6];
    const float* be1 = (const float*)d_in[7];
    const float* Wl2 = (const float*)d_in[8];
    const float* bl2 = (const float*)d_in[9];
    const float* Wr2 = (const float*)d_in[10];
    const float* g2  = (const float*)d_in[11];
    const float* be2 = (const float*)d_in[12];
    const float* Wl3 = (const float*)d_in[13];
    const float* bl3 = (const float*)d_in[14];
    const float* Wr3 = (const float*)d_in[15];
    const float* g3  = (const float*)d_in[16];
    const float* be3 = (const float*)d_in[17];
    const float* Wf1 = (const float*)d_in[18];
    const float* bf1 = (const float*)d_in[19];
    const float* Wf2 = (const float*)d_in[20];
    const float* bf2 = (const float*)d_in[21];

    int E = in_sizes[1] / 2;
    const int* src = ei;
    const int* dst = ei + E;

    void *p_h1, *p_h2, *p_h3, *p_stats;
    cudaGetSymbolAddress(&p_h1, g_h1);
    cudaGetSymbolAddress(&p_h2, g_h2);
    cudaGetSymbolAddress(&p_h3, g_h3);
    cudaGetSymbolAddress(&p_stats, g_stats);
    float* h1 = (float*)p_h1;
    float* h2 = (float*)p_h2;
    float* h3 = (float*)p_h3;
    float* st = (float*)p_stats;

    int eb = (E + 255) / 256;
    const int NB = (NNODES + 255) / 256;       // 391
    const int GB = (NNODES + 63) / 64;         // 1563 (64 nodes per block)

    k_zero<<<392, 256>>>();
    k_deg<<<eb, 256>>>(dst, batch, E);
    k_chunks<<<NCHUNK, 512>>>();
    k_scanbase<<<1, 256>>>();
    k_local<<<NCHUNK, 512>>>();
    k_fill<<<eb, 256>>>(src, dst, E);

    // layer 1
    k_layer1<<<NB, 256>>>(x, Wl1, bl1, Wr1);
    k_stats32<<<392, 256>>>(h1, st + 0, st + 32);
    k_bnrelu<32><<<392, 256>>>(h1, st + 0, st + 32, g1, be1);

    // layer 2 (stats fused)
    k_layer2<<<GB, 256>>>(h1, Wl2, bl2, Wr2, h2, st + 64, st + 128);
    k_bnrelu<64><<<392, 256>>>(h2, st + 64, st + 128, g2, be2);

    // layer 3 (stats fused, dyn smem)
    cudaFuncSetAttribute(k_layer3, cudaFuncAttributeMaxDynamicSharedMemorySize, SM3_FLOATS * 4);
    k_layer3<<<GB, 256, SM3_FLOATS * 4>>>(h2, Wl3, bl3, Wr3, h3, st + 192, st + 320);

    // fused bn3 + relu + pool, then head
    k_bnpool<<<(NNODES * 32) / 256, 256>>>(batch, st + 192, st + 320, g3, be3);
    k_mlp<<<NGRAPHS, 128>>>(Wf1, bf1, Wf2, bf2, (float*)d_out);
}

// round 4
// speedup vs baseline: 1.7544x; 1.0664x over previous
#include <cuda_runtime.h>
#include <cstdint>

#define NNODES  100000
#define NEDGES  1600000
#define NGRAPHS 64
#define EPS     1e-5f
#define NCHUNK  ((NNODES + 511) / 512)   // 196

typedef unsigned long long u64;

// ---------------- device scratch ----------------
__device__ int   g_deg [NNODES];
__device__ int   g_roff[NNODES];
__device__ int   g_cur [NNODES];
__device__ int   g_csr [NEDGES];
__device__ int   g_bsum [256];
__device__ __align__(16) float g_h1[NNODES * 32];
__device__ __align__(16) float g_h2[NNODES * 64];
__device__ __align__(16) float g_h3[(size_t)NNODES * 128];
__device__ __align__(16) float g_stats[448];   // L1 sum@0 sq@32 | L2 sum@64 sq@128 | L3 sum@192 sq@320
__device__ __align__(16) float g_pool[NGRAPHS * 128];
__device__ float g_cntg[NGRAPHS];

// ---------------- helpers ----------------
__device__ __forceinline__ u64 ffma2(u64 a, u64 b, u64 c) {
    u64 d;
    asm("fma.rn.f32x2 %0, %1, %2, %3;" : "=l"(d) : "l"(a), "l"(b), "l"(c));
    return d;
}
__device__ __forceinline__ u64 pack2(float lo, float hi) {
    u64 r;
    asm("mov.b64 %0, {%1, %2};" : "=l"(r) : "f"(lo), "f"(hi));
    return r;
}
__device__ __forceinline__ float2 unpack2(u64 v) {
    float2 r;
    asm("mov.b64 {%0, %1}, %2;" : "=f"(r.x), "=f"(r.y) : "l"(v));
    return r;
}
__device__ __forceinline__ void red_f32(float* addr, float v) {
    asm volatile("red.global.add.f32 [%0], %1;" :: "l"(addr), "f"(v) : "memory");
}
__device__ __forceinline__ void red_add_v4(float* addr, float a, float b, float c, float d) {
    asm volatile("red.global.add.v4.f32 [%0], {%1,%2,%3,%4};"
                 :: "l"(addr), "f"(a), "f"(b), "f"(c), "f"(d) : "memory");
}

// ---------------- zero scratch ----------------
__global__ void k_zero() {
    int i = blockIdx.x * blockDim.x + threadIdx.x;
    int stride = gridDim.x * blockDim.x;
    for (int j = i; j < NNODES; j += stride) g_deg[j] = 0;
    if (i < 448) g_stats[i] = 0.f;
    if (i < NGRAPHS * 128) g_pool[i] = 0.f;
    if (i < NGRAPHS) g_cntg[i] = 0.f;
}

// ---------------- CSR build (+ per-graph node counts) ----------------
__global__ void k_deg(const int* __restrict__ dst, const int* __restrict__ batch, int e) {
    int i = blockIdx.x * blockDim.x + threadIdx.x;
    if (i < e) atomicAdd(&g_deg[dst[i]], 1);
    if (i < NNODES) {
        int g = batch[i];
        unsigned act = __activemask();
        unsigned mask = __match_any_sync(act, g);
        int leader = __ffs(mask) - 1;
        if ((threadIdx.x & 31) == leader) atomicAdd(&g_cntg[g], (float)__popc(mask));
    }
}

__global__ void k_chunks() {
    __shared__ int s[512];
    int tid = threadIdx.x;
    int i = blockIdx.x * 512 + tid;
    s[tid] = (i < NNODES) ? g_deg[i] : 0;
    __syncthreads();
    for (int off = 256; off > 0; off >>= 1) {
        if (tid < off) s[tid] += s[tid + off];
        __syncthreads();
    }
    if (tid == 0) g_bsum[blockIdx.x] = s[0];
}

// merged: every block re-scans the 196 chunk sums itself, then local-scans its 512 degs
__global__ void k_scan() {
    __shared__ int sb[256];
    __shared__ int s[512];
    int tid = threadIdx.x;
    if (tid < 256) sb[tid] = (tid < NCHUNK) ? g_bsum[tid] : 0;
    int i = blockIdx.x * 512 + tid;
    int v = (i < NNODES) ? g_deg[i] : 0;
    s[tid] = v;
    __syncthreads();
    // inclusive scan of chunk sums (first 256 threads)
    for (int off = 1; off < 256; off <<= 1) {
        int t = 0;
        if (tid < 256 && tid >= off) t = sb[tid - off];
        __syncthreads();
        if (tid < 256) sb[tid] += t;
        __syncthreads();
    }
    // inclusive scan of this chunk's degrees
    for (int off = 1; off < 512; off <<= 1) {
        int t = (tid >= off) ? s[tid - off] : 0;
        __syncthreads();
        s[tid] += t;
        __syncthreads();
    }
    if (i < NNODES) {
        int base = (blockIdx.x > 0) ? sb[blockIdx.x - 1] : 0;
        int r = base + s[tid] - v;
        g_roff[i] = r;
        g_cur[i]  = r;
    }
}

__global__ void k_fill(const int* __restrict__ src, const int* __restrict__ dst, int e) {
    int i = blockIdx.x * blockDim.x + threadIdx.x;
    if (i < e) {
        int d = dst[i];
        int pos = atomicAdd(&g_cur[d], 1);
        g_csr[pos] = src[i];
    }
}

// ---------------- layer 1: 2 -> 32, thread/node, stats fused ----------------
__global__ __launch_bounds__(256) void k_layer1(const float* __restrict__ x,
                                                const float* __restrict__ Wl,
                                                const float* __restrict__ bl,
                                                const float* __restrict__ Wr,
                                                float* __restrict__ gsum, float* __restrict__ gsq) {
    __shared__ float sWl[64], sWr[64], sbl[32];
    __shared__ float sRed[512];   // 8 warps × (32 sum + 32 sq)
    int tid = threadIdx.x, lane = tid & 31, w = tid >> 5;
    if (tid < 64) { sWl[tid] = Wl[tid]; sWr[tid] = Wr[tid]; }
    if (tid < 32) sbl[tid] = bl[tid];
    __syncthreads();
    int n = blockIdx.x * 256 + tid;
    bool active = (n < NNODES);
    const float2* x2 = (const float2*)x;
    float a0 = 0.f, a1 = 0.f;
    float2 xv = make_float2(0.f, 0.f);
    if (active) {
        int st = g_roff[n], d = g_deg[n];
        int k = 0;
        for (; k + 8 <= d; k += 8) {
            int si[8];
#pragma unroll
            for (int j = 0; j < 8; j++) si[j] = g_csr[st + k + j];
            float2 v[8];
#pragma unroll
            for (int j = 0; j < 8; j++) v[j] = x2[si[j]];
#pragma unroll
            for (int j = 0; j < 8; j++) { a0 += v[j].x; a1 += v[j].y; }
        }
        for (; k < d; ++k) { float2 v = x2[g_csr[st + k]]; a0 += v.x; a1 += v.y; }
        float inv = 1.f / (float)max(d, 1);
        a0 *= inv; a1 *= inv;
        xv = x2[n];
    }
    float z[32];
#pragma unroll
    for (int j = 0; j < 32; j++)
        z[j] = active ? (sbl[j] + a0 * sWl[j] + a1 * sWl[32 + j] + xv.x * sWr[j] + xv.y * sWr[32 + j]) : 0.f;
    if (active) {
        float* outp = &g_h1[n * 32];
#pragma unroll
        for (int j = 0; j < 32; j += 4)
            *(float4*)&outp[j] = make_float4(z[j], z[j + 1], z[j + 2], z[j + 3]);
    }
    // fused BN stats: warp butterfly per channel; lane c keeps channel c
    float ws = 0.f, wq = 0.f;
#pragma unroll
    for (int c = 0; c < 32; c++) {
        float s = z[c];
        float q = z[c] * z[c];
#pragma unroll
        for (int o = 16; o; o >>= 1) {
            s += __shfl_xor_sync(0xffffffffu, s, o);
            q += __shfl_xor_sync(0xffffffffu, q, o);
        }
        if (lane == c) { ws = s; wq = q; }
    }
    sRed[w * 64 + lane]      = ws;
    sRed[w * 64 + 32 + lane] = wq;
    __syncthreads();
    if (tid < 64) {
        int c = tid & 31;
        int off = (tid >= 32) ? 32 : 0;
        float a = 0.f;
#pragma unroll
        for (int w2 = 0; w2 < 8; w2++) a += sRed[w2 * 64 + off + c];
        red_f32((tid >= 32) ? &gsq[c] : &gsum[c], a);
    }
}

// ---------------- fused finalize + bn + relu (in place) ----------------
template <int D>
__global__ __launch_bounds__(256) void k_bnrelu(float* __restrict__ z,
                                                const float* __restrict__ gsum, const float* __restrict__ gsq,
                                                const float* __restrict__ gam, const float* __restrict__ bet) {
    __shared__ float ssc[D], ssh[D];
    int tid = threadIdx.x;
    if (tid < D) {
        float mean = gsum[tid] * (1.f / NNODES);
        float var  = gsq[tid] * (1.f / NNODES) - mean * mean;
        float sc = gam[tid] * rsqrtf(var + EPS);
        ssc[tid] = sc;
        ssh[tid] = bet[tid] - mean * sc;
    }
    __syncthreads();
    constexpr int CPG = D / 4;
    const int total = NNODES * CPG;
    float4* z4 = (float4*)z;
    for (int idx = blockIdx.x * blockDim.x + tid; idx < total; idx += gridDim.x * blockDim.x) {
        int c = (idx % CPG) * 4;
        float4 v = z4[idx];
        float4 sc = *(const float4*)&ssc[c];
        float4 sh = *(const float4*)&ssh[c];
        v.x = fmaxf(v.x * sc.x + sh.x, 0.f);
        v.y = fmaxf(v.y * sc.y + sh.y, 0.f);
        v.z = fmaxf(v.z * sc.z + sh.z, 0.f);
        v.w = fmaxf(v.w * sc.w + sh.w, 0.f);
        z4[idx] = v;
    }
}

// ---------------- layer 2: 32 -> 64, 64 nodes/block, fused stats ----------------
__global__ __launch_bounds__(256) void k_layer2(const float* __restrict__ hin,
                                                const float* __restrict__ Wl,
                                                const float* __restrict__ bl,
                                                const float* __restrict__ Wr,
                                                float* __restrict__ out,
                                                float* __restrict__ gsum, float* __restrict__ gsq) {
    __shared__ float sWl[2048], sWr[2048], sbl[64];
    __shared__ float sAX[64 * 64];   // row rr: [rr*64 + 2*i]={agg_i, x_i}
    int tid = threadIdx.x, lane = tid & 31, w = tid >> 5;
    for (int i = tid; i < 2048; i += 256) { sWl[i] = Wl[i]; sWr[i] = Wr[i]; }
    if (tid < 64) sbl[tid] = bl[tid];
    int base = blockIdx.x * 64;
    for (int r = 0; r < 8; r++) {
        int rr = w * 8 + r;
        int node = base + rr;
        float2 axv = make_float2(0.f, 0.f);
        if (node < NNODES) {
            int st = g_roff[node], d = g_deg[node];
            float acc = 0.f;
            int k = 0;
            for (; k + 8 <= d; k += 8) {
                int si[8];
#pragma unroll
                for (int j = 0; j < 8; j++) si[j] = g_csr[st + k + j];
                float v[8];
#pragma unroll
                for (int j = 0; j < 8; j++) v[j] = hin[si[j] * 32 + lane];
#pragma unroll
                for (int j = 0; j < 8; j++) acc += v[j];
            }
            for (; k < d; ++k) acc += hin[g_csr[st + k] * 32 + lane];
            axv.x = acc * (1.f / (float)max(d, 1));
            axv.y = hin[node * 32 + lane];
        }
        *(float2*)&sAX[rr * 64 + 2 * lane] = axv;
    }
    __syncthreads();
    u64 acc[8];
    {
        u64 b = *(const u64*)&sbl[2 * lane];
#pragma unroll
        for (int r = 0; r < 8; r++) acc[r] = b;
    }
#pragma unroll 4
    for (int i = 0; i < 32; i++) {
        u64 wl = *(const u64*)&sWl[i * 64 + 2 * lane];
        u64 wr = *(const u64*)&sWr[i * 64 + 2 * lane];
#pragma unroll
        for (int r = 0; r < 8; r++) {
            float2 ax = *(const float2*)&sAX[(w * 8 + r) * 64 + 2 * i];
            acc[r] = ffma2(pack2(ax.x, ax.x), wl, acc[r]);
            acc[r] = ffma2(pack2(ax.y, ax.y), wr, acc[r]);
        }
    }
    float s0 = 0.f, s1 = 0.f, q0 = 0.f, q1 = 0.f;
#pragma unroll
    for (int r = 0; r < 8; r++) {
        int node = base + w * 8 + r;
        if (node < NNODES) {
            float2 v = unpack2(acc[r]);
            *(float2*)&out[node * 64 + 2 * lane] = v;
            s0 += v.x; s1 += v.y; q0 += v.x * v.x; q1 += v.y * v.y;
        }
    }
    __syncthreads();
    float* sRed = sAX;  // [w][0..63]=sum, [w][64..127]=sq
    sRed[w * 128 + 2 * lane]     = s0;
    sRed[w * 128 + 2 * lane + 1] = s1;
    sRed[w * 128 + 64 + 2 * lane]     = q0;
    sRed[w * 128 + 64 + 2 * lane + 1] = q1;
    __syncthreads();
    if (tid < 128) {
        int c = tid & 63;
        int off = (tid >= 64) ? 64 : 0;
        float a = 0.f;
#pragma unroll
        for (int w2 = 0; w2 < 8; w2++) a += sRed[w2 * 128 + off + c];
        red_f32((tid >= 64) ? &gsq[c] : &gsum[c], a);
    }
}

// ---------------- layer 3: 64 -> 128, weights via L1 (__ldg), static smem ----------------
__global__ __launch_bounds__(256) void k_layer3(const float* __restrict__ hin,
                                                const float* __restrict__ Wl,
                                                const float* __restrict__ bl,
                                                const float* __restrict__ Wr,
                                                float* __restrict__ out,
                                                float* __restrict__ gsum, float* __restrict__ gsq) {
    __shared__ float sAX[64 * 128];   // 32 KB; row rr: [rr*128 + 2*i]={agg_i, x_i}; reused for reduce
    int tid = threadIdx.x, lane = tid & 31, w = tid >> 5;
    int base = blockIdx.x * 64;
    const float2* h2v = (const float2*)hin;
    for (int r = 0; r < 8; r++) {
        int rr = w * 8 + r;
        int node = base + rr;
        float4 axv = make_float4(0.f, 0.f, 0.f, 0.f);
        if (node < NNODES) {
            int st = g_roff[node], d = g_deg[node];
            float a0 = 0.f, a1 = 0.f;
            int k = 0;
            for (; k + 8 <= d; k += 8) {
                int si[8];
#pragma unroll
                for (int j = 0; j < 8; j++) si[j] = g_csr[st + k + j];
                float2 v[8];
#pragma unroll
                for (int j = 0; j < 8; j++) v[j] = h2v[si[j] * 32 + lane];
#pragma unroll
                for (int j = 0; j < 8; j++) { a0 += v[j].x; a1 += v[j].y; }
            }
            for (; k < d; ++k) { float2 v = h2v[g_csr[st + k] * 32 + lane]; a0 += v.x; a1 += v.y; }
            float inv = 1.f / (float)max(d, 1);
            float2 hx = h2v[node * 32 + lane];
            axv = make_float4(a0 * inv, hx.x, a1 * inv, hx.y);
        }
        *(float4*)&sAX[rr * 128 + 4 * lane] = axv;
    }
    __syncthreads();
    const ulonglong2* Wl2 = (const ulonglong2*)Wl;  // row i, lane -> cols 4*lane..+3
    const ulonglong2* Wr2 = (const ulonglong2*)Wr;
    u64 a01[8], a23[8];
    {
        ulonglong2 b2 = __ldg((const ulonglong2*)bl + lane);
#pragma unroll
        for (int r = 0; r < 8; r++) { a01[r] = b2.x; a23[r] = b2.y; }
    }
#pragma unroll 2
    for (int i = 0; i < 64; i++) {
        ulonglong2 wl = __ldg(Wl2 + i * 32 + lane);
        ulonglong2 wr = __ldg(Wr2 + i * 32 + lane);
#pragma unroll
        for (int r = 0; r < 8; r++) {
            float2 ax = *(const float2*)&sAX[(w * 8 + r) * 128 + 2 * i];
            u64 A = pack2(ax.x, ax.x);
            u64 X = pack2(ax.y, ax.y);
            a01[r] = ffma2(A, wl.x, a01[r]);
            a23[r] = ffma2(A, wl.y, a23[r]);
            a01[r] = ffma2(X, wr.x, a01[r]);
            a23[r] = ffma2(X, wr.y, a23[r]);
        }
    }
    float s[4] = {0.f, 0.f, 0.f, 0.f}, q[4] = {0.f, 0.f, 0.f, 0.f};
#pragma unroll
    for (int r = 0; r < 8; r++) {
        int node = base + w * 8 + r;
        if (node < NNODES) {
            float2 v01 = unpack2(a01[r]);
            float2 v23 = unpack2(a23[r]);
            *(float4*)&out[(size_t)node * 128 + 4 * lane] = make_float4(v01.x, v01.y, v23.x, v23.y);
            s[0] += v01.x; s[1] += v01.y; s[2] += v23.x; s[3] += v23.y;
            q[0] += v01.x * v01.x; q[1] += v01.y * v01.y; q[2] += v23.x * v23.x; q[3] += v23.y * v23.y;
        }
    }
    __syncthreads();
    float* sRed = sAX;   // [w][0..127]=sum, [w][128..255]=sq (stride 256)
#pragma unroll
    for (int k = 0; k < 4; k++) {
        sRed[w * 256 + 4 * lane + k]       = s[k];
        sRed[w * 256 + 128 + 4 * lane + k] = q[k];
    }
    __syncthreads();
    {
        int c = tid & 127;
        int off = (tid >= 128) ? 128 : 0;
        float a = 0.f;
#pragma unroll
        for (int w2 = 0; w2 < 8; w2++) a += sRed[w2 * 256 + off + c];
        red_f32((tid >= 128) ? &gsq[c] : &gsum[c], a);
    }
}

// ---------------- fused finalize3 + bn + relu + pool ----------------
__global__ __launch_bounds__(256) void k_bnpool(const int* __restrict__ batch,
                                                const float* __restrict__ gsum, const float* __restrict__ gsq,
                                                const float* __restrict__ gam, const float* __restrict__ bet) {
    __shared__ float ssc[128], ssh[128];
    int tid = threadIdx.x;
    if (tid < 128) {
        float mean = gsum[tid] * (1.f / NNODES);
        float var  = gsq[tid] * (1.f / NNODES) - mean * mean;
        float sc = gam[tid] * rsqrtf(var + EPS);
        ssc[tid] = sc;
        ssh[tid] = bet[tid] - mean * sc;
    }
    __syncthreads();
    int idx = blockIdx.x * 256 + tid;
    int row = idx >> 5, c4 = idx & 31;
    int c = c4 * 4;
    float4 v = ((const float4*)g_h3)[idx];
    float4 sc = *(const float4*)&ssc[c];
    float4 sh = *(const float4*)&ssh[c];
    v.x = fmaxf(v.x * sc.x + sh.x, 0.f);
    v.y = fmaxf(v.y * sc.y + sh.y, 0.f);
    v.z = fmaxf(v.z * sc.z + sh.z, 0.f);
    v.w = fmaxf(v.w * sc.w + sh.w, 0.f);
    int g = batch[row];
    red_add_v4(&g_pool[g * 128 + c], v.x, v.y, v.z, v.w);
}

// ---------------- head MLP ----------------
__global__ void k_mlp(const float* __restrict__ Wf1, const float* __restrict__ bf1,
                      const float* __restrict__ Wf2, const float* __restrict__ bf2,
                      float* __restrict__ out) {
    __shared__ float sp[128];
    __shared__ float sh[64];
    int g = blockIdx.x, tid = threadIdx.x;
    float inv = 1.f / fmaxf(g_cntg[g], 1.f);
    sp[tid] = g_pool[g * 128 + tid] * inv;
    __syncthreads();
    if (tid < 64) {
        float acc = bf1[tid];
#pragma unroll 8
        for (int i = 0; i < 128; i++) acc += sp[i] * Wf1[i * 64 + tid];
        acc = fmaxf(acc, 0.f);
        sh[tid] = acc * Wf2[tid];
    }
    __syncthreads();
    if (tid < 32) {
        float v = sh[tid] + sh[tid + 32];
        for (int o = 16; o; o >>= 1) v += __shfl_down_sync(0xffffffffu, v, o);
        if (tid == 0) out[g] = v + bf2[0];
    }
}

// ---------------- launch ----------------
extern "C" void kernel_launch(void* const* d_in, const int* in_sizes, int n_in,
                              void* d_out, int out_size) {
    const float* x     = (const float*)d_in[0];
    const int*   ei    = (const int*)d_in[1];
    const int*   batch = (const int*)d_in[2];
    const float* Wl1 = (const float*)d_in[3];
    const float* bl1 = (const float*)d_in[4];
    const float* Wr1 = (const float*)d_in[5];
    const float* g1  = (const float*)d_in[6];
    const float* be1 = (const float*)d_in[7];
    const float* Wl2 = (const float*)d_in[8];
    const float* bl2 = (const float*)d_in[9];
    const float* Wr2 = (const float*)d_in[10];
    const float* g2  = (const float*)d_in[11];
    const float* be2 = (const float*)d_in[12];
    const float* Wl3 = (const float*)d_in[13];
    const float* bl3 = (const float*)d_in[14];
    const float* Wr3 = (const float*)d_in[15];
    const float* g3  = (const float*)d_in[16];
    const float* be3 = (const float*)d_in[17];
    const float* Wf1 = (const float*)d_in[18];
    const float* bf1 = (const float*)d_in[19];
    const float* Wf2 = (const float*)d_in[20];
    const float* bf2 = (const float*)d_in[21];

    int E = in_sizes[1] / 2;
    const int* src = ei;
    const int* dst = ei + E;

    void *p_h1, *p_h2, *p_h3, *p_stats;
    cudaGetSymbolAddress(&p_h1, g_h1);
    cudaGetSymbolAddress(&p_h2, g_h2);
    cudaGetSymbolAddress(&p_h3, g_h3);
    cudaGetSymbolAddress(&p_stats, g_stats);
    float* h1 = (float*)p_h1;
    float* h2 = (float*)p_h2;
    float* h3 = (float*)p_h3;
    float* st = (float*)p_stats;

    int eb = (E + 255) / 256;
    const int NB = (NNODES + 255) / 256;       // 391
    const int GB = (NNODES + 63) / 64;         // 1563

    k_zero<<<392, 256>>>();
    k_deg<<<eb, 256>>>(dst, batch, E);
    k_chunks<<<NCHUNK, 512>>>();
    k_scan<<<NCHUNK, 512>>>();
    k_fill<<<eb, 256>>>(src, dst, E);

    // layer 1 (stats fused)
    k_layer1<<<NB, 256>>>(x, Wl1, bl1, Wr1, st + 0, st + 32);
    k_bnrelu<32><<<392, 256>>>(h1, st + 0, st + 32, g1, be1);

    // layer 2 (stats fused)
    k_layer2<<<GB, 256>>>(h1, Wl2, bl2, Wr2, h2, st + 64, st + 128);
    k_bnrelu<64><<<392, 256>>>(h2, st + 64, st + 128, g2, be2);

    // layer 3 (stats fused, weights via L1)
    k_layer3<<<GB, 256>>>(h2, Wl3, bl3, Wr3, h3, st + 192, st + 320);

    // fused bn3 + relu + pool, then head
    k_bnpool<<<(NNODES * 32) / 256, 256>>>(batch, st + 192, st + 320, g3, be3);
    k_mlp<<<NGRAPHS, 128>>>(Wf1, bf1, Wf2, bf2, (float*)d_out);
}